// round 16
// baseline (speedup 1.0000x reference)
#include <cuda_runtime.h>
#include <cuda_bf16.h>
#include <cuda_fp16.h>
#include <cstdint>

#define HEADS 32
#define SEQ   2048
#define DH    128
#define BM    64
#define BN    64
#define NIT   (SEQ / BN)      // 32
#define NT    128
#define NELEM (HEADS * SEQ * DH)

// scratch (device globals: sanctioned scratch, no allocs)
__device__ __align__(16) unsigned short g_qhi[NELEM];   // Q*log2(e), bf16 hi
__device__ __align__(16) unsigned short g_qlo[NELEM];   // residual, bf16
__device__ __align__(16) unsigned short g_khi[NELEM];
__device__ __align__(16) unsigned short g_klo[NELEM];
__device__ __align__(16) unsigned short g_vf[NELEM];    // V^T [head][d][s], fp16

// 2-stage smem ring; stage: KH 16K, KL 16K, V 16K
#define STG_SZ  49152u
#define S_KH    0u
#define S_KL    16384u
#define S_V     32768u
#define SMEM_MAIN (2u * STG_SZ)   // 96KB per CTA -> 2 CTAs/SM

// ---------------- PTX helpers ----------------
__device__ __forceinline__ uint32_t smem_u32(const void* p) {
    uint32_t a;
    asm("{ .reg .u64 t; cvta.to.shared.u64 t, %1; cvt.u32.u64 %0, t; }" : "=r"(a) : "l"(p));
    return a;
}
__device__ __forceinline__ void cp16(uint32_t dst, const void* src) {
    asm volatile("cp.async.cg.shared.global [%0], [%1], 16;" :: "r"(dst), "l"(src) : "memory");
}
#define CP_COMMIT() asm volatile("cp.async.commit_group;" ::: "memory")
#define CP_WAIT_0() asm volatile("cp.async.wait_group 0;" ::: "memory")
#define CP_WAIT_1() asm volatile("cp.async.wait_group 1;" ::: "memory")

#define LDSM4(r, a) \
    asm volatile("ldmatrix.sync.aligned.m8n8.x4.shared.b16 {%0,%1,%2,%3}, [%4];" \
        : "=r"((r)[0]), "=r"((r)[1]), "=r"((r)[2]), "=r"((r)[3]) : "r"(a))

#define MMAB(c, a, b0, b1) \
    asm volatile("mma.sync.aligned.m16n8k16.row.col.f32.bf16.bf16.f32 " \
        "{%0,%1,%2,%3}, {%4,%5,%6,%7}, {%8,%9}, {%0,%1,%2,%3};" \
        : "+f"((c)[0]), "+f"((c)[1]), "+f"((c)[2]), "+f"((c)[3]) \
        : "r"((a)[0]), "r"((a)[1]), "r"((a)[2]), "r"((a)[3]), "r"(b0), "r"(b1))

#define MMAH(c, a, b0, b1) \
    asm volatile("mma.sync.aligned.m16n8k16.row.col.f32.f16.f16.f32 " \
        "{%0,%1,%2,%3}, {%4,%5,%6,%7}, {%8,%9}, {%0,%1,%2,%3};" \
        : "+f"((c)[0]), "+f"((c)[1]), "+f"((c)[2]), "+f"((c)[3]) \
        : "r"((a)[0]), "r"((a)[1]), "r"((a)[2]), "r"((a)[3]), "r"(b0), "r"(b1))

__device__ __forceinline__ uint32_t pack_f16x2(float x, float y) {
    uint32_t d;
    asm("cvt.rn.f16x2.f32 %0, %1, %2;" : "=r"(d) : "f"(y), "f"(x));
    return d;
}
__device__ __forceinline__ float ex2(float x) {
    float r;
    asm("ex2.approx.f32 %0, %1;" : "=f"(r) : "f"(x));
    return r;
}

// ---------------- hi/lo split ----------------
__device__ __forceinline__ void split1(float v, unsigned short& h, unsigned short& l) {
    uint32_t b = __float_as_uint(v);
    h = (unsigned short)(b >> 16);
    float r = v - __uint_as_float(b & 0xffff0000u);
    l = __bfloat16_as_ushort(__float2bfloat16(r));
}

#define LOG2E 1.44269504088896340736f

// ---------------- fused prepass: V^T transpose + QK hi/lo split ----------------
__global__ void prepass_kernel(const float* __restrict__ Q, const float* __restrict__ K,
                               const float* __restrict__ V,
                               unsigned short* __restrict__ qh, unsigned short* __restrict__ ql,
                               unsigned short* __restrict__ kh, unsigned short* __restrict__ kl,
                               unsigned short* __restrict__ vf) {
    __shared__ float t[32][33];
    int h = blockIdx.z, s0 = blockIdx.x * 32, d0 = blockIdx.y * 32;
    int tx = threadIdx.x, ty = threadIdx.y;
    const float* src = V + ((size_t)h * SEQ + s0) * DH + d0;
#pragma unroll
    for (int j = 0; j < 32; j += 8)
        t[ty + j][tx] = src[(size_t)(ty + j) * DH + tx];

    {   // QK split slice: 8192 blocks x 256 threads covers NELEM/4 float4s
        int bid = (blockIdx.z * gridDim.y + blockIdx.y) * gridDim.x + blockIdx.x;
        int i = bid * 256 + ty * 32 + tx;
        unsigned short h0,h1,h2,h3,l0,l1,l2,l3;
        float4 q = reinterpret_cast<const float4*>(Q)[i];
        split1(q.x * LOG2E, h0, l0); split1(q.y * LOG2E, h1, l1);
        split1(q.z * LOG2E, h2, l2); split1(q.w * LOG2E, h3, l3);
        *reinterpret_cast<uint2*>(qh + 4*(size_t)i) =
            make_uint2((uint32_t)h0 | ((uint32_t)h1<<16), (uint32_t)h2 | ((uint32_t)h3<<16));
        *reinterpret_cast<uint2*>(ql + 4*(size_t)i) =
            make_uint2((uint32_t)l0 | ((uint32_t)l1<<16), (uint32_t)l2 | ((uint32_t)l3<<16));
        float4 k = reinterpret_cast<const float4*>(K)[i];
        split1(k.x,h0,l0); split1(k.y,h1,l1); split1(k.z,h2,l2); split1(k.w,h3,l3);
        *reinterpret_cast<uint2*>(kh + 4*(size_t)i) =
            make_uint2((uint32_t)h0 | ((uint32_t)h1<<16), (uint32_t)h2 | ((uint32_t)h3<<16));
        *reinterpret_cast<uint2*>(kl + 4*(size_t)i) =
            make_uint2((uint32_t)l0 | ((uint32_t)l1<<16), (uint32_t)l2 | ((uint32_t)l3<<16));
    }

    __syncthreads();
#pragma unroll
    for (int j = 0; j < 32; j += 8) {
        __half hv = __float2half_rn(t[tx][ty + j]);
        size_t o = ((size_t)h * DH + d0 + ty + j) * SEQ + s0 + tx;
        vf[o] = *reinterpret_cast<unsigned short*>(&hv);
    }
}

// ---------------- stage loader (cp.async, swizzled), NT=128, BN=64 ----------------
__device__ __forceinline__ void stage_load(uint32_t stg,
                                           const unsigned short* gkh, const unsigned short* gkl,
                                           const unsigned short* gv, int tid) {
#pragma unroll
    for (int t = 0; t < 8; ++t) {
        int idx = tid + t * NT;           // 0..1023
        int r = idx >> 4, c16 = idx & 15; // K: 64 rows x 16 chunks
        uint32_t d = stg + S_KH + ((uint32_t)r << 8) + (uint32_t)((c16 ^ (r & 7)) << 4);
        cp16(d, gkh + (size_t)r * DH + c16 * 8);
        cp16(d + (S_KL - S_KH), gkl + (size_t)r * DH + c16 * 8);
    }
#pragma unroll
    for (int t = 0; t < 8; ++t) {
        int idx = tid + t * NT;
        int r = idx >> 3, c16 = idx & 7;  // V^T: 128 rows x 8 chunks
        uint32_t d = stg + S_V + ((uint32_t)r << 7) + (uint32_t)((c16 ^ (r & 7)) << 4);
        cp16(d, gv + (size_t)r * SEQ + c16 * 8);
    }
}

// ---------------- main attention kernel ----------------
// 4 warps, M-partition (16 rows/warp), 2 CTAs/SM.
// Per-j fused softmax/PV; prefetch of stage i+2 at the LOOP BOTTOM (after the
// sync that retires all reads of this buffer) — the R4/R7/R8 discipline.
__global__ __launch_bounds__(NT, 2)
void fa_hmma_kernel(float* __restrict__ Out) {
    extern __shared__ char smc[];
    const uint32_t sb = smem_u32(smc);
    const int tid  = threadIdx.x;
    const int lane = tid & 31;
    const int warp = tid >> 5;
    const int head = blockIdx.y;
    const int q0   = blockIdx.x * BM;
    const size_t base = (size_t)head * SEQ * DH;

    const unsigned short* gqh = g_qhi + base + (size_t)q0 * DH;
    const unsigned short* gql = g_qlo + base + (size_t)q0 * DH;
    const unsigned short* gkh0 = g_khi + base;
    const unsigned short* gkl0 = g_klo + base;
    const unsigned short* gv0  = g_vf + (size_t)head * DH * SEQ;

    // ---- stage Q (hi/lo) into buffer 0 area, hoist frags ----
    for (int idx = tid; idx < 1024; idx += NT) {
        int r = idx >> 4, c16 = idx & 15;
        uint32_t d = ((uint32_t)r << 8) + (uint32_t)((c16 ^ (r & 7)) << 4);
        *reinterpret_cast<uint4*>(smc + d) =
            *reinterpret_cast<const uint4*>(gqh + (size_t)r * DH + c16 * 8);
        *reinterpret_cast<uint4*>(smc + 16384u + d) =
            *reinterpret_cast<const uint4*>(gql + (size_t)r * DH + c16 * 8);
    }
    __syncthreads();

    const int r0    = warp * 16;
    const int a_row = r0 + (lane & 7) + ((lane >> 3) & 1) * 8;
    const int a_c8  = lane >> 4;
    const int axr   = a_row & 7;
    const int b_row = (lane & 7) + ((lane >> 4) << 3);
    const int b_c8  = (lane >> 3) & 1;
    const int bxr   = b_row & 7;

    uint32_t qfh[8][4], qfl[8][4];
#pragma unroll
    for (int ks = 0; ks < 8; ++ks) {
        uint32_t aaddr = sb + (uint32_t)(a_row << 8) +
                         (uint32_t)(((2 * ks + a_c8) ^ axr) << 4);
        LDSM4(qfh[ks], aaddr);
        LDSM4(qfl[ks], aaddr + 16384u);
    }
    __syncthreads();   // Q frags in regs; smem free for the ring

    // prefetch stages 0, 1
    stage_load(sb,          gkh0,           gkl0,           gv0,      tid);
    CP_COMMIT();
    stage_load(sb + STG_SZ, gkh0 + BN * DH, gkl0 + BN * DH, gv0 + BN, tid);
    CP_COMMIT();

    float co[16][4];
#pragma unroll
    for (int i = 0; i < 16; ++i)
#pragma unroll
        for (int j = 0; j < 4; ++j) co[i][j] = 0.0f;
    float lsum0 = 0.0f, lsum1 = 0.0f;
    float m0 = -1e30f, m1 = -1e30f;

    for (int i = 0; i < NIT; ++i) {
        const uint32_t stg = sb + (uint32_t)(i & 1) * STG_SZ;
        if (i == NIT - 1) { CP_WAIT_0(); } else { CP_WAIT_1(); }
        __syncthreads();

        // ---- S = Q K^T (bf16 3-product hi/lo) ----
        float cs[8][4];
#pragma unroll
        for (int t = 0; t < 8; ++t)
#pragma unroll
            for (int j = 0; j < 4; ++j) cs[t][j] = 0.0f;

#pragma unroll
        for (int ks = 0; ks < 8; ++ks) {
#pragma unroll
            for (int n2 = 0; n2 < 4; ++n2) {
                uint32_t kh[4], kl[4];
                uint32_t baddr = stg + S_KH + (uint32_t)((n2 * 16 + b_row) << 8) +
                                 (uint32_t)(((2 * ks + b_c8) ^ bxr) << 4);
                LDSM4(kh, baddr);
                LDSM4(kl, baddr + (S_KL - S_KH));
                MMAB(cs[2 * n2],     qfh[ks], kh[0], kh[1]);
                MMAB(cs[2 * n2 + 1], qfh[ks], kh[2], kh[3]);
                MMAB(cs[2 * n2],     qfh[ks], kl[0], kl[1]);
                MMAB(cs[2 * n2 + 1], qfh[ks], kl[2], kl[3]);
                MMAB(cs[2 * n2],     qfl[ks], kh[0], kh[1]);
                MMAB(cs[2 * n2 + 1], qfl[ks], kh[2], kh[3]);
            }
        }

        // ---- online softmax: max + rescale, then per-j fused exp/pack/PV ----
        float tA = cs[0][0], tB = cs[0][2];
#pragma unroll
        for (int t = 0; t < 8; ++t) {
            tA = fmaxf(tA, fmaxf(cs[t][0], cs[t][1]));
            tB = fmaxf(tB, fmaxf(cs[t][2], cs[t][3]));
        }
        tA = fmaxf(tA, __shfl_xor_sync(0xffffffffu, tA, 1));
        tA = fmaxf(tA, __shfl_xor_sync(0xffffffffu, tA, 2));
        tB = fmaxf(tB, __shfl_xor_sync(0xffffffffu, tB, 1));
        tB = fmaxf(tB, __shfl_xor_sync(0xffffffffu, tB, 2));
        float mnA = fmaxf(m0, tA), mnB = fmaxf(m1, tB);
        bool upd = (mnA != m0) || (mnB != m1);
        if (__any_sync(0xffffffffu, upd)) {
            float scA = ex2(m0 - mnA), scB = ex2(m1 - mnB);
            m0 = mnA; m1 = mnB;
            lsum0 *= scA; lsum1 *= scB;
#pragma unroll
            for (int nt = 0; nt < 16; ++nt) {
                co[nt][0] *= scA; co[nt][1] *= scA;
                co[nt][2] *= scB; co[nt][3] *= scB;
            }
        }

#pragma unroll
        for (int j = 0; j < 4; ++j) {
            // exp + pack for this 16-key group (pf liveness = 4 regs)
            float e0 = ex2(cs[2*j][0]   - mnA), e1 = ex2(cs[2*j][1]   - mnA);
            float e2 = ex2(cs[2*j][2]   - mnB), e3 = ex2(cs[2*j][3]   - mnB);
            float e4 = ex2(cs[2*j+1][0] - mnA), e5 = ex2(cs[2*j+1][1] - mnA);
            float e6 = ex2(cs[2*j+1][2] - mnB), e7 = ex2(cs[2*j+1][3] - mnB);
            lsum0 += (e0 + e1) + (e4 + e5);
            lsum1 += (e2 + e3) + (e6 + e7);
            uint32_t pf[4];
            pf[0] = pack_f16x2(e0, e1);
            pf[1] = pack_f16x2(e2, e3);
            pf[2] = pack_f16x2(e4, e5);
            pf[3] = pack_f16x2(e6, e7);

            // immediately issue this group's PV HMMAs
#pragma unroll
            for (int n2 = 0; n2 < 8; ++n2) {
                uint32_t vf[4];
                uint32_t vaddr = stg + S_V + (uint32_t)((n2 * 16 + b_row) << 7) +
                                 (uint32_t)(((2 * j + b_c8) ^ bxr) << 4);
                LDSM4(vf, vaddr);
                MMAH(co[2 * n2],     pf, vf[0], vf[1]);
                MMAH(co[2 * n2 + 1], pf, vf[2], vf[3]);
            }
        }

        __syncthreads();   // all warps done reading this stage
        if (i + 2 < NIT) {
            const int key0 = (i + 2) * BN;
            stage_load(stg, gkh0 + (size_t)key0 * DH, gkl0 + (size_t)key0 * DH,
                       gv0 + key0, tid);
            CP_COMMIT();
        }
    }

    // ---- epilogue: reduce l within quads, divide, store ----
    lsum0 += __shfl_xor_sync(0xffffffffu, lsum0, 1);
    lsum0 += __shfl_xor_sync(0xffffffffu, lsum0, 2);
    lsum1 += __shfl_xor_sync(0xffffffffu, lsum1, 1);
    lsum1 += __shfl_xor_sync(0xffffffffu, lsum1, 2);
    float inv0 = 1.0f / lsum0;
    float inv1 = 1.0f / lsum1;

    float* o0 = Out + base + (size_t)(q0 + r0 + (lane >> 2)) * DH;
    float* o1 = o0 + 8 * DH;
    const int cb = (lane & 3) * 2;
#pragma unroll
    for (int nt = 0; nt < 16; ++nt) {
        int c = nt * 8 + cb;
        float2 w0 = make_float2(co[nt][0] * inv0, co[nt][1] * inv0);
        float2 w1 = make_float2(co[nt][2] * inv1, co[nt][3] * inv1);
        *reinterpret_cast<float2*>(o0 + c) = w0;
        *reinterpret_cast<float2*>(o1 + c) = w1;
    }
}

extern "C" void kernel_launch(void* const* d_in, const int* in_sizes, int n_in,
                              void* d_out, int out_size) {
    const float* Q = (const float*)d_in[0];
    const float* K = (const float*)d_in[1];
    const float* V = (const float*)d_in[2];
    float* O = (float*)d_out;

    unsigned short *qh, *ql, *kh, *kl, *vf;
    cudaGetSymbolAddress((void**)&qh, g_qhi);
    cudaGetSymbolAddress((void**)&ql, g_qlo);
    cudaGetSymbolAddress((void**)&kh, g_khi);
    cudaGetSymbolAddress((void**)&kl, g_klo);
    cudaGetSymbolAddress((void**)&vf, g_vf);

    prepass_kernel<<<dim3(SEQ / 32, DH / 32, HEADS), dim3(32, 8)>>>(
        Q, K, V, qh, ql, kh, kl, vf);

    cudaFuncSetAttribute(fa_hmma_kernel,
                         cudaFuncAttributeMaxDynamicSharedMemorySize, SMEM_MAIN);
    dim3 grid(SEQ / BM, HEADS);   // 1024 CTAs, 2 per SM
    fa_hmma_kernel<<<grid, NT, SMEM_MAIN>>>(O);
}

// round 17
// speedup vs baseline: 1.5695x; 1.5695x over previous
#include <cuda_runtime.h>
#include <cuda_bf16.h>
#include <cuda_fp16.h>
#include <cstdint>

#define HEADS 32
#define SEQ   2048
#define DH    128
#define BM    64
#define BN    64
#define NIT   (SEQ / BN)      // 32
#define NT    128
#define NELEM (HEADS * SEQ * DH)

// scratch (device globals: sanctioned scratch, no allocs)
__device__ __align__(16) unsigned short g_khi[NELEM];
__device__ __align__(16) unsigned short g_klo[NELEM];
__device__ __align__(16) unsigned short g_vf[NELEM];    // V^T [head][d][s], fp16

// 2-stage smem ring; stage: KH 16K, KL 16K, V 16K
#define STG_SZ  49152u
#define S_KH    0u
#define S_KL    16384u
#define S_V     32768u
#define SMEM_MAIN (2u * STG_SZ)   // 96KB per CTA -> 2 CTAs/SM

// ---------------- PTX helpers ----------------
__device__ __forceinline__ uint32_t smem_u32(const void* p) {
    uint32_t a;
    asm("{ .reg .u64 t; cvta.to.shared.u64 t, %1; cvt.u32.u64 %0, t; }" : "=r"(a) : "l"(p));
    return a;
}
__device__ __forceinline__ void cp16(uint32_t dst, const void* src) {
    asm volatile("cp.async.cg.shared.global [%0], [%1], 16;" :: "r"(dst), "l"(src) : "memory");
}
#define CP_COMMIT() asm volatile("cp.async.commit_group;" ::: "memory")
#define CP_WAIT_0() asm volatile("cp.async.wait_group 0;" ::: "memory")
#define CP_WAIT_1() asm volatile("cp.async.wait_group 1;" ::: "memory")

#define LDSM4(r, a) \
    asm volatile("ldmatrix.sync.aligned.m8n8.x4.shared.b16 {%0,%1,%2,%3}, [%4];" \
        : "=r"((r)[0]), "=r"((r)[1]), "=r"((r)[2]), "=r"((r)[3]) : "r"(a))

#define MMAB(c, a, b0, b1) \
    asm volatile("mma.sync.aligned.m16n8k16.row.col.f32.bf16.bf16.f32 " \
        "{%0,%1,%2,%3}, {%4,%5,%6,%7}, {%8,%9}, {%0,%1,%2,%3};" \
        : "+f"((c)[0]), "+f"((c)[1]), "+f"((c)[2]), "+f"((c)[3]) \
        : "r"((a)[0]), "r"((a)[1]), "r"((a)[2]), "r"((a)[3]), "r"(b0), "r"(b1))

#define MMAH(c, a, b0, b1) \
    asm volatile("mma.sync.aligned.m16n8k16.row.col.f32.f16.f16.f32 " \
        "{%0,%1,%2,%3}, {%4,%5,%6,%7}, {%8,%9}, {%0,%1,%2,%3};" \
        : "+f"((c)[0]), "+f"((c)[1]), "+f"((c)[2]), "+f"((c)[3]) \
        : "r"((a)[0]), "r"((a)[1]), "r"((a)[2]), "r"((a)[3]), "r"(b0), "r"(b1))

__device__ __forceinline__ uint32_t pack_f16x2(float x, float y) {
    uint32_t d;
    asm("cvt.rn.f16x2.f32 %0, %1, %2;" : "=r"(d) : "f"(y), "f"(x));
    return d;
}
__device__ __forceinline__ float ex2(float x) {
    float r;
    asm("ex2.approx.f32 %0, %1;" : "=f"(r) : "f"(x));
    return r;
}

// ---------------- hi/lo split ----------------
__device__ __forceinline__ void split1(float v, unsigned short& h, unsigned short& l) {
    uint32_t b = __float_as_uint(v);
    h = (unsigned short)(b >> 16);
    float r = v - __uint_as_float(b & 0xffff0000u);
    l = __bfloat16_as_ushort(__float2bfloat16(r));
}

#define LOG2E 1.44269504088896340736f

// ---------------- slim prepass: V^T transpose + K hi/lo split ----------------
// grid (SEQ/32, DH/32, HEADS) = 8192 blocks, block (32,8)=256 thr.
// Each block also splits 256 float4 of K (8192*256 = NELEM/4).
__global__ void prepass_kernel(const float* __restrict__ K, const float* __restrict__ V,
                               unsigned short* __restrict__ kh, unsigned short* __restrict__ kl,
                               unsigned short* __restrict__ vf) {
    __shared__ float t[32][33];
    int h = blockIdx.z, s0 = blockIdx.x * 32, d0 = blockIdx.y * 32;
    int tx = threadIdx.x, ty = threadIdx.y;
    const float* src = V + ((size_t)h * SEQ + s0) * DH + d0;
#pragma unroll
    for (int j = 0; j < 32; j += 8)
        t[ty + j][tx] = src[(size_t)(ty + j) * DH + tx];

    {   // K split slice
        int bid = (blockIdx.z * gridDim.y + blockIdx.y) * gridDim.x + blockIdx.x;
        int i = bid * 256 + ty * 32 + tx;
        unsigned short h0,h1,h2,h3,l0,l1,l2,l3;
        float4 k = reinterpret_cast<const float4*>(K)[i];
        split1(k.x,h0,l0); split1(k.y,h1,l1); split1(k.z,h2,l2); split1(k.w,h3,l3);
        *reinterpret_cast<uint2*>(kh + 4*(size_t)i) =
            make_uint2((uint32_t)h0 | ((uint32_t)h1<<16), (uint32_t)h2 | ((uint32_t)h3<<16));
        *reinterpret_cast<uint2*>(kl + 4*(size_t)i) =
            make_uint2((uint32_t)l0 | ((uint32_t)l1<<16), (uint32_t)l2 | ((uint32_t)l3<<16));
    }

    __syncthreads();
#pragma unroll
    for (int j = 0; j < 32; j += 8) {
        __half hv = __float2half_rn(t[tx][ty + j]);
        size_t o = ((size_t)h * DH + d0 + ty + j) * SEQ + s0 + tx;
        vf[o] = *reinterpret_cast<unsigned short*>(&hv);
    }
}

// ---------------- stage loader (cp.async, swizzled), NT=128, BN=64 ----------------
__device__ __forceinline__ void stage_load(uint32_t stg,
                                           const unsigned short* gkh, const unsigned short* gkl,
                                           const unsigned short* gv, int tid) {
#pragma unroll
    for (int t = 0; t < 8; ++t) {
        int idx = tid + t * NT;           // 0..1023
        int r = idx >> 4, c16 = idx & 15; // K: 64 rows x 16 chunks
        uint32_t d = stg + S_KH + ((uint32_t)r << 8) + (uint32_t)((c16 ^ (r & 7)) << 4);
        cp16(d, gkh + (size_t)r * DH + c16 * 8);
        cp16(d + (S_KL - S_KH), gkl + (size_t)r * DH + c16 * 8);
    }
#pragma unroll
    for (int t = 0; t < 8; ++t) {
        int idx = tid + t * NT;
        int r = idx >> 3, c16 = idx & 7;  // V^T: 128 rows x 8 chunks
        uint32_t d = stg + S_V + ((uint32_t)r << 7) + (uint32_t)((c16 ^ (r & 7)) << 4);
        cp16(d, gv + (size_t)r * SEQ + c16 * 8);
    }
}

// ---------------- main attention kernel (R9 schedule, verbatim loop) ----------------
// 4 warps, M-partition (16 rows/warp), 2 CTAs/SM. Q split fp32->bf16 hi/lo
// inline in the prologue (no scratch round-trip for Q).
__global__ __launch_bounds__(NT, 2)
void fa_hmma_kernel(const float* __restrict__ Q, float* __restrict__ Out) {
    extern __shared__ char smc[];
    const uint32_t sb = smem_u32(smc);
    const int tid  = threadIdx.x;
    const int lane = tid & 31;
    const int warp = tid >> 5;
    const int head = blockIdx.y;
    const int q0   = blockIdx.x * BM;
    const size_t base = (size_t)head * SEQ * DH;

    const float* gq = Q + base + (size_t)q0 * DH;
    const unsigned short* gkh0 = g_khi + base;
    const unsigned short* gkl0 = g_klo + base;
    const unsigned short* gv0  = g_vf + (size_t)head * DH * SEQ;

    // ---- stage Q: read fp32, scale by log2e, split hi/lo into smem ----
    for (int idx = tid; idx < 1024; idx += NT) {
        int r = idx >> 4, c16 = idx & 15;
        const float* s = gq + (size_t)r * DH + c16 * 8;
        float4 a = *reinterpret_cast<const float4*>(s);
        float4 b = *reinterpret_cast<const float4*>(s + 4);
        unsigned short h0,h1,h2,h3,h4,h5,h6,h7, l0,l1,l2,l3,l4,l5,l6,l7;
        split1(a.x * LOG2E, h0, l0); split1(a.y * LOG2E, h1, l1);
        split1(a.z * LOG2E, h2, l2); split1(a.w * LOG2E, h3, l3);
        split1(b.x * LOG2E, h4, l4); split1(b.y * LOG2E, h5, l5);
        split1(b.z * LOG2E, h6, l6); split1(b.w * LOG2E, h7, l7);
        uint32_t d = ((uint32_t)r << 8) + (uint32_t)((c16 ^ (r & 7)) << 4);
        uint4 hv = make_uint4((uint32_t)h0 | ((uint32_t)h1 << 16),
                              (uint32_t)h2 | ((uint32_t)h3 << 16),
                              (uint32_t)h4 | ((uint32_t)h5 << 16),
                              (uint32_t)h6 | ((uint32_t)h7 << 16));
        uint4 lv = make_uint4((uint32_t)l0 | ((uint32_t)l1 << 16),
                              (uint32_t)l2 | ((uint32_t)l3 << 16),
                              (uint32_t)l4 | ((uint32_t)l5 << 16),
                              (uint32_t)l6 | ((uint32_t)l7 << 16));
        *reinterpret_cast<uint4*>(smc + d)           = hv;
        *reinterpret_cast<uint4*>(smc + 16384u + d)  = lv;
    }
    __syncthreads();

    const int r0    = warp * 16;
    const int a_row = r0 + (lane & 7) + ((lane >> 3) & 1) * 8;   // 0..63
    const int a_c8  = lane >> 4;
    const int axr   = a_row & 7;
    const int b_row = (lane & 7) + ((lane >> 4) << 3);
    const int b_c8  = (lane >> 3) & 1;
    const int bxr   = b_row & 7;

    uint32_t qfh[8][4], qfl[8][4];
#pragma unroll
    for (int ks = 0; ks < 8; ++ks) {
        uint32_t aaddr = sb + (uint32_t)(a_row << 8) +
                         (uint32_t)(((2 * ks + a_c8) ^ axr) << 4);
        LDSM4(qfh[ks], aaddr);
        LDSM4(qfl[ks], aaddr + 16384u);
    }
    __syncthreads();   // Q frags in regs; buffer 0 free for the ring

    // prologue: load stage 0
    stage_load(sb, gkh0, gkl0, gv0, tid);
    CP_COMMIT();

    float co[16][4];
#pragma unroll
    for (int i = 0; i < 16; ++i)
#pragma unroll
        for (int j = 0; j < 4; ++j) co[i][j] = 0.0f;
    float lsum0 = 0.0f, lsum1 = 0.0f;
    float m0 = -1e30f, m1 = -1e30f;

    for (int i = 0; i < NIT; ++i) {
        const uint32_t stg = sb + (uint32_t)(i & 1) * STG_SZ;
        const uint32_t stg_next = sb + (uint32_t)((i + 1) & 1) * STG_SZ;

        CP_WAIT_0();       // stage i complete (only pending group)
        __syncthreads();   // all warps done with compute(i-1) -> stg_next free

        if (i + 1 < NIT) {
            const int key0 = (i + 1) * BN;
            stage_load(stg_next, gkh0 + (size_t)key0 * DH, gkl0 + (size_t)key0 * DH,
                       gv0 + key0, tid);
            CP_COMMIT();
        }

        // ---- S = Q K^T (bf16 3-product hi/lo) ----
        float cs[8][4];
#pragma unroll
        for (int t = 0; t < 8; ++t)
#pragma unroll
            for (int j = 0; j < 4; ++j) cs[t][j] = 0.0f;

#pragma unroll
        for (int ks = 0; ks < 8; ++ks) {
#pragma unroll
            for (int n2 = 0; n2 < 4; ++n2) {
                uint32_t kh[4], kl[4];
                uint32_t baddr = stg + S_KH + (uint32_t)((n2 * 16 + b_row) << 8) +
                                 (uint32_t)(((2 * ks + b_c8) ^ bxr) << 4);
                LDSM4(kh, baddr);
                LDSM4(kl, baddr + (S_KL - S_KH));
                MMAB(cs[2 * n2],     qfh[ks], kh[0], kh[1]);
                MMAB(cs[2 * n2 + 1], qfh[ks], kh[2], kh[3]);
                MMAB(cs[2 * n2],     qfh[ks], kl[0], kl[1]);
                MMAB(cs[2 * n2 + 1], qfh[ks], kl[2], kl[3]);
                MMAB(cs[2 * n2],     qfl[ks], kh[0], kh[1]);
                MMAB(cs[2 * n2 + 1], qfl[ks], kh[2], kh[3]);
            }
        }

        // ---- online softmax (log2 units, ex2) ----
        float tA = cs[0][0], tB = cs[0][2];
#pragma unroll
        for (int t = 0; t < 8; ++t) {
            tA = fmaxf(tA, fmaxf(cs[t][0], cs[t][1]));
            tB = fmaxf(tB, fmaxf(cs[t][2], cs[t][3]));
        }
        tA = fmaxf(tA, __shfl_xor_sync(0xffffffffu, tA, 1));
        tA = fmaxf(tA, __shfl_xor_sync(0xffffffffu, tA, 2));
        tB = fmaxf(tB, __shfl_xor_sync(0xffffffffu, tB, 1));
        tB = fmaxf(tB, __shfl_xor_sync(0xffffffffu, tB, 2));
        float mnA = fmaxf(m0, tA), mnB = fmaxf(m1, tB);
        bool upd = (mnA != m0) || (mnB != m1);
        if (__any_sync(0xffffffffu, upd)) {
            float scA = ex2(m0 - mnA), scB = ex2(m1 - mnB);
            m0 = mnA; m1 = mnB;
            lsum0 *= scA; lsum1 *= scB;
#pragma unroll
            for (int nt = 0; nt < 16; ++nt) {
                co[nt][0] *= scA; co[nt][1] *= scA;
                co[nt][2] *= scB; co[nt][3] *= scB;
            }
        }

        uint32_t pf[4][4];
#pragma unroll
        for (int j = 0; j < 4; ++j) {
            float e0 = ex2(cs[2*j][0]   - mnA), e1 = ex2(cs[2*j][1]   - mnA);
            float e2 = ex2(cs[2*j][2]   - mnB), e3 = ex2(cs[2*j][3]   - mnB);
            float e4 = ex2(cs[2*j+1][0] - mnA), e5 = ex2(cs[2*j+1][1] - mnA);
            float e6 = ex2(cs[2*j+1][2] - mnB), e7 = ex2(cs[2*j+1][3] - mnB);
            lsum0 += (e0 + e1) + (e4 + e5);
            lsum1 += (e2 + e3) + (e6 + e7);
            pf[j][0] = pack_f16x2(e0, e1);
            pf[j][1] = pack_f16x2(e2, e3);
            pf[j][2] = pack_f16x2(e4, e5);
            pf[j][3] = pack_f16x2(e6, e7);
        }

        // ---- O += P V (single fp16 product) ----
#pragma unroll
        for (int j = 0; j < 4; ++j) {
#pragma unroll
            for (int n2 = 0; n2 < 8; ++n2) {
                uint32_t vf[4];
                uint32_t vaddr = stg + S_V + (uint32_t)((n2 * 16 + b_row) << 7) +
                                 (uint32_t)(((2 * j + b_c8) ^ bxr) << 4);
                LDSM4(vf, vaddr);
                MMAH(co[2 * n2],     pf[j], vf[0], vf[1]);
                MMAH(co[2 * n2 + 1], pf[j], vf[2], vf[3]);
            }
        }
    }

    // ---- epilogue: reduce l within quads, divide, store ----
    lsum0 += __shfl_xor_sync(0xffffffffu, lsum0, 1);
    lsum0 += __shfl_xor_sync(0xffffffffu, lsum0, 2);
    lsum1 += __shfl_xor_sync(0xffffffffu, lsum1, 1);
    lsum1 += __shfl_xor_sync(0xffffffffu, lsum1, 2);
    float inv0 = 1.0f / lsum0;
    float inv1 = 1.0f / lsum1;

    float* o0 = Out + base + (size_t)(q0 + r0 + (lane >> 2)) * DH;
    float* o1 = o0 + 8 * DH;
    const int cb = (lane & 3) * 2;
#pragma unroll
    for (int nt = 0; nt < 16; ++nt) {
        int c = nt * 8 + cb;
        float2 w0 = make_float2(co[nt][0] * inv0, co[nt][1] * inv0);
        float2 w1 = make_float2(co[nt][2] * inv1, co[nt][3] * inv1);
        *reinterpret_cast<float2*>(o0 + c) = w0;
        *reinterpret_cast<float2*>(o1 + c) = w1;
    }
}

extern "C" void kernel_launch(void* const* d_in, const int* in_sizes, int n_in,
                              void* d_out, int out_size) {
    const float* Q = (const float*)d_in[0];
    const float* K = (const float*)d_in[1];
    const float* V = (const float*)d_in[2];
    float* O = (float*)d_out;

    unsigned short *kh, *kl, *vf;
    cudaGetSymbolAddress((void**)&kh, g_khi);
    cudaGetSymbolAddress((void**)&kl, g_klo);
    cudaGetSymbolAddress((void**)&vf, g_vf);

    prepass_kernel<<<dim3(SEQ / 32, DH / 32, HEADS), dim3(32, 8)>>>(K, V, kh, kl, vf);

    cudaFuncSetAttribute(fa_hmma_kernel,
                         cudaFuncAttributeMaxDynamicSharedMemorySize, SMEM_MAIN);
    dim3 grid(SEQ / BM, HEADS);   // (32, 32) = 1024 CTAs, 2 per SM
    fa_hmma_kernel<<<grid, NT, SMEM_MAIN>>>(Q, O);
}